// round 14
// baseline (speedup 1.0000x reference)
#include <cuda_runtime.h>
#include <cstdint>

#define TT   256
#define BB   32
#define NTHR 256
#define NBLK 128
#define SA   36                  // act row stride (floats)
#define REGF (128 * SA)          // region: rows 0-31 x | 32-95 h1 | 96-127 h2

// shared layout (float offsets)
#define OFF_W1 0                 // [96][256] split-half permuted
#define OFF_W2 24576             // [96][128] split-half permuted
#define OFF_B1 36864             // [256]
#define OFF_B2 37120             // [128]
#define OFF_R  37248             // 2 regions + pad
#define SMEM_FLOATS (OFF_R + 2 * REGF + 2 * SA)
#define SMEM_BYTES  (SMEM_FLOATS * 4)   // ~186 KB

__device__ __forceinline__ void fma2(uint64_t& d, uint64_t a, uint64_t b) {
    asm("fma.rn.f32x2 %0, %1, %2, %0;" : "+l"(d) : "l"(a), "l"(b));
}
__device__ __forceinline__ float2 u2f2(uint64_t u) {
    float2 f; asm("mov.b64 {%0, %1}, %2;" : "=f"(f.x), "=f"(f.y) : "l"(u)); return f;
}
__device__ __forceinline__ uint64_t f2u2(float x, float y) {
    uint64_t u; asm("mov.b64 %0, {%1, %2};" : "=l"(u) : "f"(x), "f"(y)); return u;
}
__device__ __forceinline__ float mtanh(float x) {
    float y; asm("tanh.approx.f32 %0, %1;" : "=f"(y) : "f"(x)); return y;
}
__device__ __forceinline__ float sigf(float x) {
    return fmaf(0.5f, mtanh(0.5f * x), 0.5f);
}

__device__ __forceinline__ void cellup(uint64_t gi, uint64_t gf, uint64_t gg, uint64_t go,
                                       uint64_t& cst, float2& h) {
    float2 iv = u2f2(gi), fv = u2f2(gf), gv = u2f2(gg), ov = u2f2(go), cv = u2f2(cst);
    float c0 = sigf(fv.x) * cv.x + sigf(iv.x) * mtanh(gv.x);
    float c1 = sigf(fv.y) * cv.y + sigf(iv.y) * mtanh(gv.y);
    cst = f2u2(c0, c1);
    h.x = sigf(ov.x) * mtanh(c0);
    h.y = sigf(ov.y) * mtanh(c1);
}

// 16 packed FMAs: 4 batches x 4 gate-pairs
__device__ __forceinline__ void fma_b4(uint64_t (&acc)[4][4],
                                       const ulonglong2& w0, const ulonglong2& w1,
                                       const float4& a0) {
    float av[4] = {a0.x, a0.y, a0.z, a0.w};
    #pragma unroll
    for (int b = 0; b < 4; b++) {
        uint64_t ad = f2u2(av[b], av[b]);
        fma2(acc[b][0], ad, w0.x); fma2(acc[b][1], ad, w0.y);
        fma2(acc[b][2], ad, w1.x); fma2(acc[b][3], ad, w1.y);
    }
}
// 8 packed FMAs: 2 batches x 4 gate-pairs
__device__ __forceinline__ void fma_b2(uint64_t (&acc)[2][4],
                                       const ulonglong2& w0, const ulonglong2& w1,
                                       const float2& a0) {
    float av[2] = {a0.x, a0.y};
    #pragma unroll
    for (int b = 0; b < 2; b++) {
        uint64_t ad = f2u2(av[b], av[b]);
        fma2(acc[b][0], ad, w0.x); fma2(acc[b][1], ad, w0.y);
        fma2(acc[b][2], ad, w1.x); fma2(acc[b][3], ad, w1.y);
    }
}

// L1 k-loop: 96 k, weights stride 256, acts stride SA, double-buffered
__device__ __forceinline__ void kloop_l1(uint64_t (&acc)[4][4],
                                         const float* __restrict__ wp,
                                         const float* __restrict__ ap) {
    ulonglong2 w0a = *(const ulonglong2*)wp;
    ulonglong2 w1a = *(const ulonglong2*)(wp + 128);
    float4 a0a = *(const float4*)ap;
    #pragma unroll 2
    for (int k = 0; k < 96; k += 2) {
        ulonglong2 w0b = *(const ulonglong2*)(wp + 256);
        ulonglong2 w1b = *(const ulonglong2*)(wp + 384);
        float4 a0b = *(const float4*)(ap + SA);
        fma_b4(acc, w0a, w1a, a0a);
        w0a = *(const ulonglong2*)(wp + 512);   // overrun -> W2 region, in-bounds
        w1a = *(const ulonglong2*)(wp + 640);
        a0a = *(const float4*)(ap + 2 * SA);    // overrun rows 96-97 exist
        fma_b4(acc, w0b, w1b, a0b);
        wp += 512; ap += 2 * SA;
    }
}
// L2 k-loop: 96 k, weights stride 128, acts stride SA
__device__ __forceinline__ void kloop_l2(uint64_t (&acc)[2][4],
                                         const float* __restrict__ wp,
                                         const float* __restrict__ ap) {
    ulonglong2 w0a = *(const ulonglong2*)wp;
    ulonglong2 w1a = *(const ulonglong2*)(wp + 64);
    float2 a0a = *(const float2*)ap;
    #pragma unroll 2
    for (int k = 0; k < 96; k += 2) {
        ulonglong2 w0b = *(const ulonglong2*)(wp + 128);
        ulonglong2 w1b = *(const ulonglong2*)(wp + 192);
        float2 a0b = *(const float2*)(ap + SA);
        fma_b2(acc, w0a, w1a, a0a);
        w0a = *(const ulonglong2*)(wp + 256);   // overrun -> bias region, in-bounds
        w1a = *(const ulonglong2*)(wp + 320);
        a0a = *(const float2*)(ap + 2 * SA);    // overrun rows 128-129 = pad/region
        fma_b2(acc, w0b, w1b, a0b);
        wp += 256; ap += 2 * SA;
    }
}

__global__ void __launch_bounds__(NTHR, 1)
lstm_pipe_kernel(const float* __restrict__ x,
                 const float* __restrict__ Wih1, const float* __restrict__ Whh1,
                 const float* __restrict__ bih1, const float* __restrict__ bhh1,
                 const float* __restrict__ Wih2, const float* __restrict__ Whh2,
                 const float* __restrict__ bih2, const float* __restrict__ bhh2,
                 const float* __restrict__ Whead, const float* __restrict__ bhead,
                 float* __restrict__ out)
{
    extern __shared__ float sm[];
    const int tid = threadIdx.x;

    // ---- weights: L1 row k = [i/f half: jp*4][g/o half at +128], j-pair (2jp, 2jp+1)
    for (int idx = tid; idx < 96 * 256; idx += NTHR) {
        int k = idx >> 8, c = idx & 255;
        int half = c >> 7, r = c & 127;
        int jp = r >> 2, g2 = (r >> 1) & 1, jl = r & 1;
        int gate = half * 2 + g2;
        int grow = gate * 64 + jp * 2 + jl;
        sm[OFF_W1 + idx] = (k < 32) ? Wih1[grow * 32 + k] : Whh1[grow * 64 + (k - 32)];
    }
    for (int idx = tid; idx < 96 * 128; idx += NTHR) {
        int k = idx >> 7, c = idx & 127;
        int half = c >> 6, r = c & 63;
        int jp = r >> 2, g2 = (r >> 1) & 1, jl = r & 1;
        int gate = half * 2 + g2;
        int grow = gate * 32 + jp * 2 + jl;
        sm[OFF_W2 + idx] = (k < 64) ? Wih2[grow * 64 + k] : Whh2[grow * 32 + (k - 64)];
    }
    {   // biases in acc order: jp*8 + gate*2 + jl
        int c = tid, jp = c >> 3, g = (c >> 1) & 3, jl = c & 1;
        int grow = g * 64 + jp * 2 + jl;
        sm[OFF_B1 + c] = bih1[grow] + bhh1[grow];
    }
    if (tid < 128) {
        int c = tid, jp = c >> 3, g = (c >> 1) & 3, jl = c & 1;
        int grow = g * 32 + jp * 2 + jl;
        sm[OFF_B2 + c] = bih2[grow] + bhh2[grow];
    }
    for (int idx = tid; idx < 2 * REGF + 2 * SA; idx += NTHR) sm[OFF_R + idx] = 0.0f;
    __syncthreads();
    // x[0] -> region0 rows 0..31 (4 floats/thread)
    const int xb = tid >> 3, xq = tid & 7;
    const float* xg0 = x + ((size_t)(blockIdx.x * BB + xb) * TT) * 32 + xq * 4;
    {
        float4 v = *(const float4*)xg0;
        float* d = sm + OFF_R;
        int f0 = xq * 4;
        d[(f0 + 0) * SA + xb] = v.x; d[(f0 + 1) * SA + xb] = v.y;
        d[(f0 + 2) * SA + xb] = v.z; d[(f0 + 3) * SA + xb] = v.w;
    }
    __syncthreads();

    // ---- balanced mapping: every warp does both layers ----
    const int lane = tid & 31;
    const int wd   = tid >> 5;
    const int jp1 = wd * 4 + (lane >> 3);   // 0..31; L1 j-pair (2jp1, 2jp1+1)
    const int cb1 = (lane & 7) * 4;         // L1 batches cb1..cb1+3
    const int jp2 = wd * 2 + (lane >> 4);   // 0..15; L2 j-pair
    const int cb2 = (lane & 15) * 2;        // L2 batches cb2..cb2+1

    uint64_t bias1[4], bias2[4];
    {
        ulonglong2 a = *(const ulonglong2*)(sm + OFF_B1 + jp1 * 8);
        ulonglong2 b = *(const ulonglong2*)(sm + OFF_B1 + jp1 * 8 + 4);
        bias1[0] = a.x; bias1[1] = a.y; bias1[2] = b.x; bias1[3] = b.y;
        ulonglong2 c = *(const ulonglong2*)(sm + OFF_B2 + jp2 * 8);
        ulonglong2 d = *(const ulonglong2*)(sm + OFF_B2 + jp2 * 8 + 4);
        bias2[0] = c.x; bias2[1] = c.y; bias2[2] = d.x; bias2[3] = d.y;
    }
    uint64_t c1s[4] = {0,0,0,0};
    uint64_t c2s[2] = {0,0};
    const float* wb1 = sm + OFF_W1 + jp1 * 4;
    const float* wb2 = sm + OFF_W2 + jp2 * 4;

    // ================= prologue: s = 0 (L1 only) =================
    {
        const float* rr = sm + OFF_R;            // region0
        float* wrg = sm + OFF_R + REGF;          // region1
        float4 pv = *(const float4*)(xg0 + 32);  // x(1)
        uint64_t acc1[4][4];
        #pragma unroll
        for (int b = 0; b < 4; b++) {
            acc1[b][0] = bias1[0]; acc1[b][1] = bias1[1];
            acc1[b][2] = bias1[2]; acc1[b][3] = bias1[3];
        }
        kloop_l1(acc1, wb1, rr + cb1);
        float2 hv1[4];
        #pragma unroll
        for (int b = 0; b < 4; b++)
            cellup(acc1[b][0], acc1[b][1], acc1[b][2], acc1[b][3], c1s[b], hv1[b]);
        float* hd = wrg + 32 * SA;
        int j0 = 2 * jp1;
        *(float4*)&hd[j0 * SA + cb1]       = make_float4(hv1[0].x, hv1[1].x, hv1[2].x, hv1[3].x);
        *(float4*)&hd[(j0 + 1) * SA + cb1] = make_float4(hv1[0].y, hv1[1].y, hv1[2].y, hv1[3].y);
        int f0 = xq * 4;
        wrg[(f0 + 0) * SA + xb] = pv.x; wrg[(f0 + 1) * SA + xb] = pv.y;
        wrg[(f0 + 2) * SA + xb] = pv.z; wrg[(f0 + 3) * SA + xb] = pv.w;
        __syncthreads();
    }

    // ================= steady state: s = 1 .. TT-1 =================
    for (int s = 1; s < TT; s++) {
        const float* rr = sm + OFF_R + (s & 1) * REGF;
        float* wrg = sm + OFF_R + ((s + 1) & 1) * REGF;
        float4 pv;
        const bool dopf = (s + 1 < TT);
        if (dopf) pv = *(const float4*)(xg0 + (size_t)(s + 1) * 32);

        // L1: gates(s) from x(s)+h1(s-1)
        uint64_t acc1[4][4];
        #pragma unroll
        for (int b = 0; b < 4; b++) {
            acc1[b][0] = bias1[0]; acc1[b][1] = bias1[1];
            acc1[b][2] = bias1[2]; acc1[b][3] = bias1[3];
        }
        kloop_l1(acc1, wb1, rr + cb1);
        float2 hv1[4];
        #pragma unroll
        for (int b = 0; b < 4; b++)
            cellup(acc1[b][0], acc1[b][1], acc1[b][2], acc1[b][3], c1s[b], hv1[b]);

        // L2: gates(s-1) from h1(s-1)+h2(s-2)  (independent of cellups above)
        uint64_t acc2[2][4];
        #pragma unroll
        for (int b = 0; b < 2; b++) {
            acc2[b][0] = bias2[0]; acc2[b][1] = bias2[1];
            acc2[b][2] = bias2[2]; acc2[b][3] = bias2[3];
        }
        kloop_l2(acc2, wb2, rr + 32 * SA + cb2);

        // h1(s) stores
        {
            float* hd = wrg + 32 * SA;
            int j0 = 2 * jp1;
            *(float4*)&hd[j0 * SA + cb1]       = make_float4(hv1[0].x, hv1[1].x, hv1[2].x, hv1[3].x);
            *(float4*)&hd[(j0 + 1) * SA + cb1] = make_float4(hv1[0].y, hv1[1].y, hv1[2].y, hv1[3].y);
        }
        // L2 cellup + h2(s-1) stores
        {
            float2 hv2[2];
            #pragma unroll
            for (int b = 0; b < 2; b++)
                cellup(acc2[b][0], acc2[b][1], acc2[b][2], acc2[b][3], c2s[b], hv2[b]);
            float* hd = wrg + 96 * SA;
            int j0 = 2 * jp2;
            *(float2*)&hd[j0 * SA + cb2]       = make_float2(hv2[0].x, hv2[1].x);
            *(float2*)&hd[(j0 + 1) * SA + cb2] = make_float2(hv2[0].y, hv2[1].y);
        }
        if (dopf) {
            int f0 = xq * 4;
            wrg[(f0 + 0) * SA + xb] = pv.x; wrg[(f0 + 1) * SA + xb] = pv.y;
            wrg[(f0 + 2) * SA + xb] = pv.z; wrg[(f0 + 3) * SA + xb] = pv.w;
        }
        __syncthreads();
    }

    // ================= epilogue: s = TT (L2 only -> h2(TT-1)) =================
    {
        const float* rr = sm + OFF_R;            // region0 (TT&1 = 0)
        float* wrg = sm + OFF_R + REGF;          // region1
        uint64_t acc2[2][4];
        #pragma unroll
        for (int b = 0; b < 2; b++) {
            acc2[b][0] = bias2[0]; acc2[b][1] = bias2[1];
            acc2[b][2] = bias2[2]; acc2[b][3] = bias2[3];
        }
        kloop_l2(acc2, wb2, rr + 32 * SA + cb2);
        float2 hv2[2];
        #pragma unroll
        for (int b = 0; b < 2; b++)
            cellup(acc2[b][0], acc2[b][1], acc2[b][2], acc2[b][3], c2s[b], hv2[b]);
        float* hd = wrg + 96 * SA;
        int j0 = 2 * jp2;
        *(float2*)&hd[j0 * SA + cb2]       = make_float2(hv2[0].x, hv2[1].x);
        *(float2*)&hd[(j0 + 1) * SA + cb2] = make_float2(hv2[0].y, hv2[1].y);
        __syncthreads();
    }

    // ---- head: h2[TT-1] in region 1, rows 96..127 ----
    if (tid < 96) {
        int b = tid / 3, n = tid % 3;
        const float* h2p = sm + OFF_R + REGF + 96 * SA;
        float accv = bhead[n];
        #pragma unroll
        for (int j = 0; j < 32; j++)
            accv += h2p[j * SA + b] * Whead[n * 32 + j];
        out[(size_t)(blockIdx.x * BB + b) * 3 + n] = accv;
    }
}

extern "C" void kernel_launch(void* const* d_in, const int* in_sizes, int n_in,
                              void* d_out, int out_size) {
    (void)in_sizes; (void)n_in; (void)out_size;
    const float* x     = (const float*)d_in[0];
    const float* Wih1  = (const float*)d_in[1];
    const float* Whh1  = (const float*)d_in[2];
    const float* bih1  = (const float*)d_in[3];
    const float* bhh1  = (const float*)d_in[4];
    const float* Wih2  = (const float*)d_in[5];
    const float* Whh2  = (const float*)d_in[6];
    const float* bih2  = (const float*)d_in[7];
    const float* bhh2  = (const float*)d_in[8];
    const float* Whead = (const float*)d_in[9];
    const float* bhead = (const float*)d_in[10];
    float* out = (float*)d_out;

    cudaFuncSetAttribute(lstm_pipe_kernel,
                         cudaFuncAttributeMaxDynamicSharedMemorySize, SMEM_BYTES);
    lstm_pipe_kernel<<<NBLK, NTHR, SMEM_BYTES>>>(
        x, Wih1, Whh1, bih1, bhh1, Wih2, Whh2, bih2, bhh2, Whead, bhead, out);
}

// round 17
// speedup vs baseline: 3.1510x; 3.1510x over previous
#include <cuda_runtime.h>
#include <cuda_bf16.h>
#include <cstdint>

#define TT 256
#define BB 32
#define NTHR 256
#define NBLK 128
#define RSWB 208      // weight row stride bytes (104 bf16)
#define ASB  272      // act row stride bytes (136 bf16)

// smem byte offsets
#define SW1  0                        // W1: 256 x 208
#define SW2  53248                    // W2: 128 x 208
#define ACT0 79872                    // 32 x 272
#define ACT1 88576
#define SHB  97280                    // h2 final f32 [32][33]
#define SMEM_TOTAL (SHB + 32 * 33 * 4 + 64)

__device__ __forceinline__ uint32_t smem_u32(const void* p) {
    uint32_t a; asm("{ .reg .u64 t; cvta.to.shared.u64 t, %1; cvt.u32.u64 %0, t; }" : "=r"(a) : "l"(p)); return a;
}
__device__ __forceinline__ float mtanh(float v) { float y; asm("tanh.approx.f32 %0, %1;" : "=f"(y) : "f"(v)); return y; }
__device__ __forceinline__ float sigf(float v) { return fmaf(0.5f, mtanh(0.5f * v), 0.5f); }
__device__ __forceinline__ uint32_t f2bf2(float lo, float hi) {
    uint32_t r; asm("cvt.rn.bf16x2.f32 %0, %1, %2;" : "=r"(r) : "f"(hi), "f"(lo)); return r;
}
__device__ __forceinline__ void ldsm4(uint32_t (&r)[4], uint32_t a) {
    asm volatile("ldmatrix.sync.aligned.m8n8.x4.shared.b16 {%0,%1,%2,%3}, [%4];"
                 : "=r"(r[0]), "=r"(r[1]), "=r"(r[2]), "=r"(r[3]) : "r"(a));
}
__device__ __forceinline__ void mmab(float (&d)[4], const uint32_t (&a)[4], uint32_t b0, uint32_t b1) {
    asm volatile("mma.sync.aligned.m16n8k16.row.col.f32.bf16.bf16.f32 "
                 "{%0,%1,%2,%3}, {%4,%5,%6,%7}, {%8,%9}, {%0,%1,%2,%3};"
                 : "+f"(d[0]), "+f"(d[1]), "+f"(d[2]), "+f"(d[3])
                 : "r"(a[0]), "r"(a[1]), "r"(a[2]), "r"(a[3]), "r"(b0), "r"(b1));
}

__global__ void __launch_bounds__(NTHR, 1)
lstm_hmma_kernel(const float* __restrict__ x,
                 const float* __restrict__ Wih1, const float* __restrict__ Whh1,
                 const float* __restrict__ bih1, const float* __restrict__ bhh1,
                 const float* __restrict__ Wih2, const float* __restrict__ Whh2,
                 const float* __restrict__ bih2, const float* __restrict__ bhh2,
                 const float* __restrict__ Whead, const float* __restrict__ bhead,
                 float* __restrict__ out)
{
    extern __shared__ char smc[];
    const uint32_t sb = smem_u32(smc);
    const int tid = threadIdx.x, lane = tid & 31, w = tid >> 5;

    // ---- W1 -> smem bf16 [gr=gate*64+j][k], stride 208B ----
    for (int idx = tid; idx < 256 * 96; idx += NTHR) {
        int gr = idx / 96, k = idx - gr * 96;
        float v = (k < 32) ? Wih1[gr * 32 + k] : Whh1[gr * 64 + (k - 32)];
        *(__nv_bfloat16*)(smc + SW1 + gr * RSWB + k * 2) = __float2bfloat16(v);
    }
    // ---- W2 -> smem bf16 [gr2=gate*32+j][k] ----
    for (int idx = tid; idx < 128 * 96; idx += NTHR) {
        int gr = idx / 96, k = idx - gr * 96;
        float v = (k < 64) ? Wih2[gr * 64 + k] : Whh2[gr * 32 + (k - 64)];
        *(__nv_bfloat16*)(smc + SW2 + gr * RSWB + k * 2) = __float2bfloat16(v);
    }
    // zero both act buffers (17408 B)
    for (int i = tid; i < 4352; i += NTHR) ((uint32_t*)(smc + ACT0))[i] = 0;
    __syncthreads();

    // x(0) -> act0 rows (batch-major, bf16)
    const int xb = tid >> 3, kq = tid & 7;
    const float* xg0 = x + ((size_t)(blockIdx.x * BB + xb) * TT) * 32 + kq * 4;
    {
        float4 v = *(const float4*)xg0;
        *(uint2*)(smc + ACT0 + xb * ASB + kq * 8) =
            make_uint2(f2bf2(v.x, v.y), f2bf2(v.z, v.w));
    }
    __syncthreads();

    // ---- warp roles ----
    const int g = lane >> 2, tig = lane & 3;
    const int jb = w & 3, nh = w >> 2;       // L1: j-block, n-half
    const int jb2 = w & 1, nt2 = w >> 1;     // L2
    const int j0 = jb * 16 + g;
    const int j20 = jb2 * 16 + g;

    float b1r[4][2], b2r[4][2];
    #pragma unroll
    for (int gt = 0; gt < 4; gt++) {
        b1r[gt][0] = bih1[gt * 64 + j0] + bhh1[gt * 64 + j0];
        b1r[gt][1] = bih1[gt * 64 + j0 + 8] + bhh1[gt * 64 + j0 + 8];
        b2r[gt][0] = bih2[gt * 32 + j20] + bhh2[gt * 32 + j20];
        b2r[gt][1] = bih2[gt * 32 + j20 + 8] + bhh2[gt * 32 + j20 + 8];
    }

    // ldmatrix lane addressing
    const uint32_t aRow = (uint32_t)((lane & 7) + ((lane >> 3) & 1) * 8);
    const uint32_t aCol = (uint32_t)((lane >> 4) * 16);
    const uint32_t a1addr = sb + SW1 + (jb * 16 + aRow) * RSWB + aCol;
    const uint32_t a2addr = sb + SW2 + (jb2 * 16 + aRow) * RSWB + aCol;
    // B (acts, [batch][k]) loaded NON-trans: lanes 0-7 -> 8 n-rows @k+0,
    // lanes 8-15 @k+8, 16-23 @k+16, 24-31 @k+24 (bK in bytes)
    const uint32_t bRow = (uint32_t)(lane & 7);
    const uint32_t bK = (uint32_t)((lane >> 3) * 16);
    const uint32_t bl1[2] = { (8u * (2 * nh) + bRow) * ASB + bK,
                              (8u * (2 * nh + 1) + bRow) * ASB + bK };
    const uint32_t bl2 = (8u * nt2 + bRow) * ASB + bK;

    const uint32_t actb[2] = { sb + ACT0, sb + ACT1 };
    char* const actc[2] = { smc + ACT0, smc + ACT1 };
    float* const hbp = (float*)(smc + SHB);
    float c1s[8] = {0,0,0,0,0,0,0,0};
    float c2s[4] = {0,0,0,0};

    for (int s = 0; s <= TT; s++) {
        const int cur = s & 1, nxt = cur ^ 1;
        const uint32_t rr = actb[cur];
        char* const wn = actc[nxt];

        if (s < TT) {   // ---- L1: gates(s) = W1 * [x(s); h1(s-1)] ----
            uint32_t bf1[2][3][4];
            #pragma unroll
            for (int nt = 0; nt < 2; nt++)
                #pragma unroll
                for (int kp = 0; kp < 3; kp++)
                    ldsm4(bf1[nt][kp], rr + bl1[nt] + kp * 64);

            float acc1[4][2][4];
            #pragma unroll
            for (int gt = 0; gt < 4; gt++)
                #pragma unroll
                for (int nt = 0; nt < 2; nt++) {
                    acc1[gt][nt][0] = b1r[gt][0]; acc1[gt][nt][1] = b1r[gt][0];
                    acc1[gt][nt][2] = b1r[gt][1]; acc1[gt][nt][3] = b1r[gt][1];
                }
            #pragma unroll
            for (int gt = 0; gt < 4; gt++)
                #pragma unroll
                for (int kc = 0; kc < 6; kc++) {
                    uint32_t af[4];
                    ldsm4(af, a1addr + gt * 13312 + kc * 32);
                    mmab(acc1[gt][0], af, bf1[0][kc >> 1][(kc & 1) * 2], bf1[0][kc >> 1][(kc & 1) * 2 + 1]);
                    mmab(acc1[gt][1], af, bf1[1][kc >> 1][(kc & 1) * 2], bf1[1][kc >> 1][(kc & 1) * 2 + 1]);
                }
            // cellup L1 -> h1(s) bf16 into wn cols 32+j
            #pragma unroll
            for (int jsel = 0; jsel < 2; jsel++)
                #pragma unroll
                for (int nt = 0; nt < 2; nt++)
                    #pragma unroll
                    for (int e = 0; e < 2; e++) {
                        int ri = jsel * 2 + e, ci = jsel * 4 + nt * 2 + e;
                        float gi = acc1[0][nt][ri], gf = acc1[1][nt][ri];
                        float gg = acc1[2][nt][ri], go = acc1[3][nt][ri];
                        float c = sigf(gf) * c1s[ci] + sigf(gi) * mtanh(gg);
                        c1s[ci] = c;
                        float h = sigf(go) * mtanh(c);
                        int b = 8 * (2 * nh + nt) + 2 * tig + e;
                        *(__nv_bfloat16*)(wn + b * ASB + (32 + j0 + jsel * 8) * 2) = __float2bfloat16(h);
                    }
        }

        if (s >= 1) {   // ---- L2: gates(s-1) = W2 * [h1(s-1); h2(s-2)] ----
            uint32_t bf2[3][4];
            #pragma unroll
            for (int kp = 0; kp < 3; kp++)
                ldsm4(bf2[kp], rr + bl2 + 64 + kp * 64);   // act cols 32..127

            float acc2[4][4];
            #pragma unroll
            for (int gt = 0; gt < 4; gt++) {
                acc2[gt][0] = b2r[gt][0]; acc2[gt][1] = b2r[gt][0];
                acc2[gt][2] = b2r[gt][1]; acc2[gt][3] = b2r[gt][1];
            }
            #pragma unroll
            for (int gt = 0; gt < 4; gt++)
                #pragma unroll
                for (int kc = 0; kc < 6; kc++) {
                    uint32_t af[4];
                    ldsm4(af, a2addr + gt * 6656 + kc * 32);
                    mmab(acc2[gt], af, bf2[kc >> 1][(kc & 1) * 2], bf2[kc >> 1][(kc & 1) * 2 + 1]);
                }
            #pragma unroll
            for (int jsel = 0; jsel < 2; jsel++)
                #pragma unroll
                for (int e = 0; e < 2; e++) {
                    int ri = jsel * 2 + e, ci = jsel * 2 + e;
                    float gi = acc2[0][ri], gf = acc2[1][ri];
                    float gg = acc2[2][ri], go = acc2[3][ri];
                    float c = sigf(gf) * c2s[ci] + sigf(gi) * mtanh(gg);
                    c2s[ci] = c;
                    float h = sigf(go) * mtanh(c);
                    int b = 8 * nt2 + 2 * tig + e;
                    int j2 = j20 + jsel * 8;
                    if (s < TT) *(__nv_bfloat16*)(wn + b * ASB + (96 + j2) * 2) = __float2bfloat16(h);
                    else        hbp[b * 33 + j2] = h;
                }
        }

        if (s + 1 < TT) {   // x(s+1) prefetch -> wn
            float4 v = *(const float4*)(xg0 + (size_t)(s + 1) * 32);
            *(uint2*)(wn + xb * ASB + kq * 8) =
                make_uint2(f2bf2(v.x, v.y), f2bf2(v.z, v.w));
        }
        __syncthreads();
    }

    // ---- head: out[b][n] = h2[TT-1][b] . W_head[n] + b_head[n] ----
    if (tid < 96) {
        int b = tid / 3, n = tid % 3;
        float acc = bhead[n];
        #pragma unroll
        for (int j = 0; j < 32; j++) acc += hbp[b * 33 + j] * Whead[n * 32 + j];
        out[(size_t)(blockIdx.x * BB + b) * 3 + n] = acc;
    }
}

extern "C" void kernel_launch(void* const* d_in, const int* in_sizes, int n_in,
                              void* d_out, int out_size) {
    (void)in_sizes; (void)n_in; (void)out_size;
    cudaFuncSetAttribute(lstm_hmma_kernel, cudaFuncAttributeMaxDynamicSharedMemorySize, SMEM_TOTAL);
    lstm_hmma_kernel<<<NBLK, NTHR, SMEM_TOTAL>>>(
        (const float*)d_in[0], (const float*)d_in[1], (const float*)d_in[2],
        (const float*)d_in[3], (const float*)d_in[4], (const float*)d_in[5],
        (const float*)d_in[6], (const float*)d_in[7], (const float*)d_in[8],
        (const float*)d_in[9], (const float*)d_in[10], (float*)d_out);
}